// round 7
// baseline (speedup 1.0000x reference)
#include <cuda_runtime.h>

// out[b,s,f,o] = sum_{t,k,c} x[b, s+t-2, f*(k+1), c] * W[t,k,c,o],  f*(k+1) < F
// x [4,1024,512,4] f32, W [5,4,4,4] f32, out [4,1024,512,4] f32.
//
// R7: R6 (c-packed FFMA2, ring buffer, __constant__ weights, 64-reg cap)
//     + warp-chunk f-interleave: each block gets 4 heavy (f<256, all k) and
//     4 light (f>=256, k=0 only) warps -> uniform block durations, fixing the
//     wave-packing/occupancy decay seen in R6 (occ 39.6% w/ 32-warp fit).

#define B_  4
#define S_  1024
#define F_  512
#define U_  4
#define NT  5
#define NK  4
#define TPB 256

typedef unsigned long long u64;

// Wc2[(k*NT+t)*4 + o] : floats (c0,c1,c2,c3) -> .x=(c0,c1) .y=(c2,c3)
__constant__ ulonglong2 Wc2[NK * NT * 4];
__device__ float Wt_scratch[NT * NK * 16];     // transposed weights staging

__global__ void transpose_w_kernel(const float* __restrict__ W)
{
    int i = threadIdx.x;                        // 320 threads, one element each
    if (i < NT * NK * 16) {
        // src linear: ((t*NK + k)*4 + c)*4 + o
        int o = i & 3, c = (i >> 2) & 3, k = (i >> 4) & 3, t = i >> 6;
        Wt_scratch[((k * NT + t) * 4 + o) * 4 + c] = W[i];
    }
}

__device__ __forceinline__ u64 fma2(u64 a, u64 b, u64 c) {
    u64 d;
    asm("fma.rn.f32x2 %0, %1, %2, %3;" : "=l"(d) : "l"(a), "l"(b), "l"(c));
    return d;
}

__global__ __launch_bounds__(TPB, 4) void harm_conv_kernel(
    const float* __restrict__ x,
    float* __restrict__ out)
{
    int gid = blockIdx.x * TPB + threadIdx.x;

    // f-chunk interleave: slab = (b, sb) owns 16 warp-chunks of 32 f-values.
    // chunk w (0..15) -> w' = ((w & 7) << 1) | (w >> 3): block0 -> even chunks
    // (4 heavy + 4 light), block1 -> odd chunks. Warp stays f-contiguous.
    int lane = gid & 31;
    int w    = (gid >> 5) & 15;
    int wp   = ((w & 7) << 1) | (w >> 3);
    int f    = (wp << 5) | lane;

    int sb = (gid >> 9) & (S_ / U_ - 1);
    int b  = gid >> 17;
    int s0 = sb * U_;

    const ulonglong2* __restrict__ xb =
        reinterpret_cast<const ulonglong2*>(x) + (size_t)b * S_ * F_;

    u64 acc[U_][4];                            // [j][o], packed over c-pairs
#pragma unroll
    for (int j = 0; j < U_; ++j)
#pragma unroll
        for (int o = 0; o < 4; ++o) acc[j][o] = 0ull;

    for (int k = 0; k < NK; ++k) {
        int fk = f * (k + 1);
        if (fk >= F_) break;                   // monotone in k, warp-coherent
        const ulonglong2* __restrict__ col = xb + fk;

        // ring buffer: w4[m & 3] holds row m (sp = s0 + m - 2), m = 0..7
        ulonglong2 w4[4];
#pragma unroll
        for (int m = 0; m < 4; ++m) {
            int sp = s0 + m - 2;
            w4[m] = (sp >= 0 && sp < S_) ? col[(size_t)sp * F_]
                                         : make_ulonglong2(0ull, 0ull);
        }

#pragma unroll
        for (int t = 0; t < NT; ++t) {
            ulonglong2 w0 = Wc2[(k * NT + t) * 4 + 0];
            ulonglong2 w1 = Wc2[(k * NT + t) * 4 + 1];
            ulonglong2 w2 = Wc2[(k * NT + t) * 4 + 2];
            ulonglong2 w3 = Wc2[(k * NT + t) * 4 + 3];
#pragma unroll
            for (int j = 0; j < U_; ++j) {
                ulonglong2 rv = w4[(t + j) & 3];
                acc[j][0] = fma2(rv.x, w0.x, acc[j][0]);
                acc[j][1] = fma2(rv.x, w1.x, acc[j][1]);
                acc[j][2] = fma2(rv.x, w2.x, acc[j][2]);
                acc[j][3] = fma2(rv.x, w3.x, acc[j][3]);
                acc[j][0] = fma2(rv.y, w0.y, acc[j][0]);
                acc[j][1] = fma2(rv.y, w1.y, acc[j][1]);
                acc[j][2] = fma2(rv.y, w2.y, acc[j][2]);
                acc[j][3] = fma2(rv.y, w3.y, acc[j][3]);
            }
            if (t < NT - 1) {                  // load row m = t+4 into w4[t & 3]
                int sp = s0 + t + 2;
                w4[t & 3] = (sp < S_) ? col[(size_t)sp * F_]
                                      : make_ulonglong2(0ull, 0ull);
            }
        }
    }

    // epilogue: fold the two c-halves per output
    float4* __restrict__ o4 =
        reinterpret_cast<float4*>(out) + ((size_t)(b * S_ + s0)) * F_ + f;
#pragma unroll
    for (int j = 0; j < U_; ++j) {
        float2 a0 = reinterpret_cast<float2&>(acc[j][0]);
        float2 a1 = reinterpret_cast<float2&>(acc[j][1]);
        float2 a2 = reinterpret_cast<float2&>(acc[j][2]);
        float2 a3 = reinterpret_cast<float2&>(acc[j][3]);
        o4[(size_t)j * F_] = make_float4(a0.x + a0.y, a1.x + a1.y,
                                         a2.x + a2.y, a3.x + a3.y);
    }
}

extern "C" void kernel_launch(void* const* d_in, const int* in_sizes, int n_in,
                              void* d_out, int out_size)
{
    const float* x = (const float*)d_in[0];
    const float* W = (const float*)d_in[1];
    float* out = (float*)d_out;

    // 1) transpose weights into staging buffer (device-side)
    transpose_w_kernel<<<1, NT * NK * 16>>>(W);

    // 2) stage into the constant bank (capture-legal async D2D)
    void* wt_dev = nullptr;
    cudaGetSymbolAddress(&wt_dev, Wt_scratch);
    cudaMemcpyToSymbolAsync(Wc2, wt_dev, NT * NK * 16 * sizeof(float), 0,
                            cudaMemcpyDeviceToDevice, 0);

    // 3) main kernel
    int total = B_ * (S_ / U_) * F_;           // one thread per (b, s-block, f)
    harm_conv_kernel<<<total / TPB, TPB>>>(x, out);
}